// round 9
// baseline (speedup 1.0000x reference)
#include <cuda_runtime.h>
#include <cuda_bf16.h>
#include <math.h>
#include <stdint.h>

// TopKRouter: logits = x @ W^T (16384x4096 @ 4096x64), softmax, top-2, renorm.
// Split-bf16 (hi/lo) 3-product mma.sync.m16n8k16 GEMM.
// Round 9: warp = 16 tokens x 32 experts x K/2  (CTA: 2 expert-halves x 2 K-halves)
//          -> 16-reg accumulators, 6 CTAs/SM, 24 warps/SM resident.
// out fp32: [indices 16384*2][weights 16384*2][logits 16384*64]

#define TOKENS 16384
#define DIM    4096
#define NEXP   64
#define NKS    (DIM / 16)   // 256 k-steps total
#define KSH    (NKS / 2)    // 128 k-steps per warp (K half)

// Fragment-ordered pre-converted W, hi and lo interleaved:
// q = ((ks*8 + nt)*32 + lane): uint4 { hi(kb,kb+1), hi(kb+8,kb+9),
//                                      lo(kb,kb+1), lo(kb+8,kb+9) }
// with n = nt*8 + lane/4, kb = ks*16 + (lane%4)*2.
__device__ uint4 g_B[NKS * 8 * 32];

__device__ __forceinline__ void split2(float a, float b, unsigned& h, unsigned& l) {
    asm("cvt.rn.bf16x2.f32 %0, %1, %2;" : "=r"(h) : "f"(b), "f"(a));
    float ha = __uint_as_float(h << 16);
    float hb = __uint_as_float(h & 0xFFFF0000u);
    float ra = a - ha;
    float rb = b - hb;
    asm("cvt.rn.bf16x2.f32 %0, %1, %2;" : "=r"(l) : "f"(rb), "f"(ra));
}

__device__ __forceinline__ void mma16816(float* c, unsigned a0, unsigned a1,
                                         unsigned a2, unsigned a3,
                                         unsigned b0, unsigned b1) {
    asm volatile(
        "mma.sync.aligned.m16n8k16.row.col.f32.bf16.bf16.f32 "
        "{%0,%1,%2,%3}, {%4,%5,%6,%7}, {%8,%9}, {%0,%1,%2,%3};"
        : "+f"(c[0]), "+f"(c[1]), "+f"(c[2]), "+f"(c[3])
        : "r"(a0), "r"(a1), "r"(a2), "r"(a3), "r"(b0), "r"(b1));
}

// ---------------- W pre-convert (fragment order, interleaved) ----------------
__global__ void convert_w_kernel(const float* __restrict__ Wg) {
    int q = blockIdx.x * blockDim.x + threadIdx.x;   // 0..65535
    int ks   = q >> 8;
    int nt   = (q >> 5) & 7;
    int lane = q & 31;
    int n  = nt * 8 + (lane >> 2);
    int kb = ks * 16 + (lane & 3) * 2;
    const float* wr = Wg + (size_t)n * DIM + kb;
    unsigned hx, lx, hy, ly;
    split2(wr[0], wr[1], hx, lx);
    split2(wr[8], wr[9], hy, ly);
    g_B[q] = make_uint4(hx, hy, lx, ly);
}

__device__ __forceinline__ bool better(float v, int i, float v2, int i2) {
    return (v > v2) || (v == v2 && i < i2);
}

// ---------------- main kernel ----------------
// CTA: 4 warps over the same 16 tokens.
//   wid&1  = expert half (experts eh*32 .. eh*32+31)
//   wid>>1 = K half      (k-steps kh*128 .. kh*128+127)
__global__ __launch_bounds__(128, 6) void router_kernel(
    const float* __restrict__ x,
    float* __restrict__ out)
{
    __shared__ float red[2 * 32 * 17];     // K-half partials: [eh][lane][16], pad 17
    __shared__ float4 cand[2][16];         // per-half top2: {m1, i1, m2, i2}

    const int tid  = threadIdx.x;
    const int wid  = tid >> 5;
    const int lane = tid & 31;
    const int eh   = wid & 1;              // expert half
    const int kh   = wid >> 1;             // K half
    const int r0   = blockIdx.x * 16 + (lane >> 2);   // rows r0, r0+8
    const int kbase = kh * KSH;

    const float2* pA0 = (const float2*)(x + (size_t)r0 * DIM) + (lane & 3);
    const float2* pA1 = pA0 + 4 * DIM;     // row r0+8

    float acc[4][4];
    #pragma unroll
    for (int nt = 0; nt < 4; nt++)
        #pragma unroll
        for (int j = 0; j < 4; j++) acc[nt][j] = 0.0f;

    // B base for this expert half: nt_global = eh*4 + nt_local
    const uint4* __restrict__ B = g_B + lane + eh * 4 * 32;

    #pragma unroll 2
    for (int s = 0; s < KSH; s++) {
        const int ks = kbase + s;
        float2 v00 = __ldg(pA0 + ks * 8);
        float2 v01 = __ldg(pA0 + ks * 8 + 4);
        float2 v10 = __ldg(pA1 + ks * 8);
        float2 v11 = __ldg(pA1 + ks * 8 + 4);

        unsigned ah0, ah1, ah2, ah3, al0, al1, al2, al3;
        split2(v00.x, v00.y, ah0, al0);
        split2(v10.x, v10.y, ah1, al1);
        split2(v01.x, v01.y, ah2, al2);
        split2(v11.x, v11.y, ah3, al3);

        const uint4* b = B + ks * 256;
        #pragma unroll
        for (int nt = 0; nt < 4; nt++) {
            uint4 bv = __ldg(b + nt * 32);
            mma16816(acc[nt], ah0, ah1, ah2, ah3, bv.x, bv.y);   // hi*hi
            mma16816(acc[nt], ah0, ah1, ah2, ah3, bv.z, bv.w);   // hi*lo
            mma16816(acc[nt], al0, al1, al2, al3, bv.x, bv.y);   // lo*hi
        }
    }

    // ---- K-half reduction via smem (kh=1 stores, kh=0 adds) ----
    if (kh == 1) {
        float* dst = red + (eh * 32 + lane) * 17;
        #pragma unroll
        for (int nt = 0; nt < 4; nt++)
            #pragma unroll
            for (int j = 0; j < 4; j++)
                dst[nt * 4 + j] = acc[nt][j];
    }
    __syncthreads();

    if (kh == 0) {
        const float* src = red + (eh * 32 + lane) * 17;
        #pragma unroll
        for (int nt = 0; nt < 4; nt++)
            #pragma unroll
            for (int j = 0; j < 4; j++)
                acc[nt][j] += src[nt * 4 + j];

        // ---- write logits (this warp's 32 expert columns) ----
        float* lg = out + 4 * TOKENS;
        const int cbase = (lane & 3) * 2;
        #pragma unroll
        for (int nt = 0; nt < 4; nt++) {
            int c = (eh * 4 + nt) * 8 + cbase;
            *(float2*)(lg + (size_t)r0 * NEXP + c)       = make_float2(acc[nt][0], acc[nt][1]);
            *(float2*)(lg + (size_t)(r0 + 8) * NEXP + c) = make_float2(acc[nt][2], acc[nt][3]);
        }

        // ---- per-row local top-2 over this expert half ----
        #pragma unroll
        for (int half = 0; half < 2; half++) {
            float m1 = -INFINITY, m2 = -INFINITY;
            int i1 = 0, i2 = 0;
            #pragma unroll
            for (int nt = 0; nt < 4; nt++) {
                #pragma unroll
                for (int j = 0; j < 2; j++) {
                    float v = acc[nt][half * 2 + j];
                    int e = (eh * 4 + nt) * 8 + cbase + j;
                    if (v > m1)      { m2 = m1; i2 = i1; m1 = v; i1 = e; }
                    else if (v > m2) { m2 = v; i2 = e; }
                }
            }
            #pragma unroll
            for (int d = 1; d < 4; d <<= 1) {
                float om1 = __shfl_xor_sync(0xFFFFFFFF, m1, d);
                int   oi1 = __shfl_xor_sync(0xFFFFFFFF, i1, d);
                float om2 = __shfl_xor_sync(0xFFFFFFFF, m2, d);
                int   oi2 = __shfl_xor_sync(0xFFFFFFFF, i2, d);
                if (better(om1, oi1, m1, i1)) {
                    float nm2; int ni2;
                    if (better(m1, i1, om2, oi2)) { nm2 = m1; ni2 = i1; }
                    else                          { nm2 = om2; ni2 = oi2; }
                    m1 = om1; i1 = oi1; m2 = nm2; i2 = ni2;
                } else {
                    if (better(om1, oi1, m2, i2)) { m2 = om1; i2 = oi1; }
                }
            }
            if ((lane & 3) == 0) {
                int rloc = (lane >> 2) + half * 8;   // local row 0..15
                cand[eh][rloc] = make_float4(m1, (float)i1, m2, (float)i2);
            }
        }
    }
    __syncthreads();

    // ---- cross-half merge + final outputs (warp 0, 8 lanes x 2 halves) ----
    if (wid == 0 && (lane & 3) == 0) {
        #pragma unroll
        for (int half = 0; half < 2; half++) {
            int rloc = (lane >> 2) + half * 8;
            float4 c0 = cand[0][rloc];   // experts 0..31 (lower indices)
            float4 c1 = cand[1][rloc];   // experts 32..63
            float m1, m2; int i1, i2;
            // value tie -> half 0 wins (lower index), matching lax.top_k order
            if (c1.x > c0.x) {
                m1 = c1.x; i1 = (int)c1.y;
                if (c0.x >= c1.z) { m2 = c0.x; i2 = (int)c0.y; }
                else              { m2 = c1.z; i2 = (int)c1.w; }
            } else {
                m1 = c0.x; i1 = (int)c0.y;
                if (c1.x > c0.z)  { m2 = c1.x; i2 = (int)c1.y; }
                else              { m2 = c0.z; i2 = (int)c0.w; }
            }
            const size_t row = (size_t)blockIdx.x * 16 + rloc;
            // top-2 renorm of full softmax == logistic of (m1 - m2); +1e-9 negligible
            float e2 = __expf(m2 - m1);
            float rcp = 1.0f / (1.0f + e2);
            out[row * 2 + 0] = (float)i1;
            out[row * 2 + 1] = (float)i2;
            out[2 * TOKENS + row * 2 + 0] = rcp;
            out[2 * TOKENS + row * 2 + 1] = e2 * rcp;
        }
    }
}

extern "C" void kernel_launch(void* const* d_in, const int* in_sizes, int n_in,
                              void* d_out, int out_size)
{
    const float* x  = (const float*)d_in[0];
    const float* Wg = (const float*)d_in[1];
    float* out = (float*)d_out;

    convert_w_kernel<<<256, 256>>>(Wg);
    router_kernel<<<TOKENS / 16, 128>>>(x, out);
}

// round 10
// speedup vs baseline: 1.2905x; 1.2905x over previous
#include <cuda_runtime.h>
#include <cuda_bf16.h>
#include <math.h>
#include <stdint.h>

// TopKRouter: logits = x @ W^T (16384x4096 @ 4096x64), softmax, top-2, renorm.
// Split-bf16 (hi/lo) 3-product mma.sync.m16n8k16 GEMM, K-split x4 across warps.
// Round 10: R6 decomposition + 2-stage cp.async pipeline (A and B staged in
//           per-warp smem buffers) to decouple DRAM/L2 latency from registers.
// out fp32: [indices 16384*2][weights 16384*2][logits 16384*64]

#define TOKENS 16384
#define DIM    4096
#define NEXP   64
#define NKS    (DIM / 16)   // 256 k-steps total
#define KSW    (NKS / 4)    // 64 k-steps per warp

// smem layout (dynamic):
//   bufA: warp w, stage st -> w*2048 + st*1024          (4w x 2st x 1KB = 8KB)
//   bufB: 8192 + w*8192 + st*4096                        (4w x 2st x 4KB = 32KB)
//   red : 40960 (3 * 32 * 33 floats = 12672B)            total 53632B
#define SMEM_BYTES 53632

// Fragment-ordered pre-converted W, hi and lo interleaved:
// q = ((ks*8 + nt)*32 + lane): uint4 { hi(kb,kb+1), hi(kb+8,kb+9),
//                                      lo(kb,kb+1), lo(kb+8,kb+9) }
// with n = nt*8 + lane/4, kb = ks*16 + (lane%4)*2.
__device__ uint4 g_B[NKS * 8 * 32];

__device__ __forceinline__ uint32_t smem_u32(const void* p) {
    uint32_t a;
    asm("{ .reg .u64 t; cvta.to.shared.u64 t, %1; cvt.u32.u64 %0, t; }" : "=r"(a) : "l"(p));
    return a;
}

__device__ __forceinline__ void split2(float a, float b, unsigned& h, unsigned& l) {
    asm("cvt.rn.bf16x2.f32 %0, %1, %2;" : "=r"(h) : "f"(b), "f"(a));
    float ha = __uint_as_float(h << 16);
    float hb = __uint_as_float(h & 0xFFFF0000u);
    float ra = a - ha;
    float rb = b - hb;
    asm("cvt.rn.bf16x2.f32 %0, %1, %2;" : "=r"(l) : "f"(rb), "f"(ra));
}

__device__ __forceinline__ void mma16816(float* c, unsigned a0, unsigned a1,
                                         unsigned a2, unsigned a3,
                                         unsigned b0, unsigned b1) {
    asm volatile(
        "mma.sync.aligned.m16n8k16.row.col.f32.bf16.bf16.f32 "
        "{%0,%1,%2,%3}, {%4,%5,%6,%7}, {%8,%9}, {%0,%1,%2,%3};"
        : "+f"(c[0]), "+f"(c[1]), "+f"(c[2]), "+f"(c[3])
        : "r"(a0), "r"(a1), "r"(a2), "r"(a3), "r"(b0), "r"(b1));
}

__device__ __forceinline__ void cp16(uint32_t dst, const void* src) {
    asm volatile("cp.async.ca.shared.global [%0], [%1], 16;"
                 :: "r"(dst), "l"(src) : "memory");
}

// ---------------- W pre-convert (fragment order, interleaved) ----------------
__global__ void convert_w_kernel(const float* __restrict__ Wg) {
    int q = blockIdx.x * blockDim.x + threadIdx.x;   // 0..65535
    int ks   = q >> 8;
    int nt   = (q >> 5) & 7;
    int lane = q & 31;
    int n  = nt * 8 + (lane >> 2);
    int kb = ks * 16 + (lane & 3) * 2;
    const float* wr = Wg + (size_t)n * DIM + kb;
    unsigned hx, lx, hy, ly;
    split2(wr[0], wr[1], hx, lx);
    split2(wr[8], wr[9], hy, ly);
    g_B[q] = make_uint4(hx, hy, lx, ly);
}

__device__ __forceinline__ bool better(float v, int i, float v2, int i2) {
    return (v > v2) || (v == v2 && i < i2);
}

// ---------------- main kernel ----------------
// CTA: 4 warps, same 16 tokens, K quarters. Partial-acc reduce through smem.
__global__ __launch_bounds__(128, 4) void router_kernel(
    const float* __restrict__ x,
    float* __restrict__ out)
{
    extern __shared__ char sm[];
    float* red = (float*)(sm + 40960);

    const int tid  = threadIdx.x;
    const int wid  = tid >> 5;           // K quarter 0..3
    const int lane = tid & 31;
    const int r0   = blockIdx.x * 16 + (lane >> 2);   // rows r0, r0+8
    const int kbase = wid * KSW;

    const uint32_t smb   = smem_u32(sm);
    const uint32_t aBase = smb + wid * 2048;
    const uint32_t bBase = smb + 8192 + wid * 8192;

    // copy-role mapping for A: thread copies 32B (half a token row slice)
    const int ctok  = lane >> 1;         // token 0..15
    const int chalf = lane & 1;          // 0: bytes 0-31, 1: bytes 32-63
    const float* aSrcBase = x + ((size_t)blockIdx.x * 16 + ctok) * DIM + chalf * 8;
    const char*  bSrcBase = (const char*)g_B + (size_t)lane * 16;

    float acc[8][4];
    #pragma unroll
    for (int nt = 0; nt < 8; nt++)
        #pragma unroll
        for (int j = 0; j < 4; j++) acc[nt][j] = 0.0f;

    // ---- pipeline issue helper (stage = s&1) ----
    auto issue = [&](int s) {
        const int st = s & 1;
        const int ks = kbase + s;
        // A: 2 x 16B per thread (one 32B half-row of one token)
        const float* asrc = aSrcBase + (size_t)ks * 16;
        uint32_t adst = aBase + st * 1024 + ctok * 64 + chalf * 32;
        cp16(adst,      asrc);
        cp16(adst + 16, asrc + 4);
        // B: 8 x 16B per thread (own lane's fragment for each nt)
        const char* bsrc = bSrcBase + (size_t)ks * 8 * 32 * 16;
        uint32_t bdst = bBase + st * 4096 + lane * 16;
        #pragma unroll
        for (int nt = 0; nt < 8; nt++)
            cp16(bdst + nt * 512, bsrc + (size_t)nt * 32 * 16);
    };

    issue(0);
    asm volatile("cp.async.commit_group;" ::: "memory");
    issue(1);
    asm volatile("cp.async.commit_group;" ::: "memory");

    const uint32_t aRd = aBase + (lane >> 2) * 64 + (lane & 3) * 8;
    const uint32_t bRd = bBase + lane * 16;

    for (int s = 0; s < KSW; s++) {
        const int st = s & 1;
        asm volatile("cp.async.wait_group 1;" ::: "memory");
        __syncwarp();

        // LDS A fragments: rows (lane>>2) and (lane>>2)+8, k halves +0 / +32B
        float2 v00 = *(const float2*)(sm + (aRd - smb) + st * 1024);
        float2 v01 = *(const float2*)(sm + (aRd - smb) + st * 1024 + 32);
        float2 v10 = *(const float2*)(sm + (aRd - smb) + st * 1024 + 512);
        float2 v11 = *(const float2*)(sm + (aRd - smb) + st * 1024 + 544);

        unsigned ah0, ah1, ah2, ah3, al0, al1, al2, al3;
        split2(v00.x, v00.y, ah0, al0);
        split2(v10.x, v10.y, ah1, al1);
        split2(v01.x, v01.y, ah2, al2);
        split2(v11.x, v11.y, ah3, al3);

        const char* bp = sm + (bRd - smb) + st * 4096;
        #pragma unroll
        for (int nt = 0; nt < 8; nt++) {
            uint4 bv = *(const uint4*)(bp + nt * 512);
            mma16816(acc[nt], ah0, ah1, ah2, ah3, bv.x, bv.y);   // hi*hi
            mma16816(acc[nt], ah0, ah1, ah2, ah3, bv.z, bv.w);   // hi*lo
            mma16816(acc[nt], al0, al1, al2, al3, bv.x, bv.y);   // lo*hi
        }

        if (s + 2 < KSW) issue(s + 2);
        asm volatile("cp.async.commit_group;" ::: "memory");
    }
    asm volatile("cp.async.wait_group 0;" ::: "memory");
    __syncwarp();

    // ---- cross-warp K reduction via smem ----
    if (wid != 0) {
        float* dst = red + ((wid - 1) * 32 + lane) * 33;
        #pragma unroll
        for (int nt = 0; nt < 8; nt++)
            #pragma unroll
            for (int j = 0; j < 4; j++)
                dst[nt * 4 + j] = acc[nt][j];
    }
    __syncthreads();
    if (wid != 0) return;

    #pragma unroll
    for (int p = 0; p < 3; p++) {
        const float* src = red + (p * 32 + lane) * 33;
        #pragma unroll
        for (int nt = 0; nt < 8; nt++)
            #pragma unroll
            for (int j = 0; j < 4; j++)
                acc[nt][j] += src[nt * 4 + j];
    }

    // ---- write logits ----
    float* lg = out + 4 * TOKENS;
    const int cbase = (lane & 3) * 2;
    #pragma unroll
    for (int nt = 0; nt < 8; nt++) {
        int c = nt * 8 + cbase;
        *(float2*)(lg + (size_t)r0 * NEXP + c)       = make_float2(acc[nt][0], acc[nt][1]);
        *(float2*)(lg + (size_t)(r0 + 8) * NEXP + c) = make_float2(acc[nt][2], acc[nt][3]);
    }

    // ---- per-row top-2 (register scan + quad shuffle merge) ----
    #pragma unroll
    for (int half = 0; half < 2; half++) {
        const int row = r0 + half * 8;
        float m1 = -INFINITY, m2 = -INFINITY;
        int i1 = 0, i2 = 0;
        #pragma unroll
        for (int nt = 0; nt < 8; nt++) {
            #pragma unroll
            for (int j = 0; j < 2; j++) {
                float v = acc[nt][half * 2 + j];
                int e = nt * 8 + cbase + j;
                if (v > m1)      { m2 = m1; i2 = i1; m1 = v; i1 = e; }
                else if (v > m2) { m2 = v; i2 = e; }
            }
        }
        #pragma unroll
        for (int d = 1; d < 4; d <<= 1) {
            float om1 = __shfl_xor_sync(0xFFFFFFFF, m1, d);
            int   oi1 = __shfl_xor_sync(0xFFFFFFFF, i1, d);
            float om2 = __shfl_xor_sync(0xFFFFFFFF, m2, d);
            int   oi2 = __shfl_xor_sync(0xFFFFFFFF, i2, d);
            if (better(om1, oi1, m1, i1)) {
                float nm2; int ni2;
                if (better(m1, i1, om2, oi2)) { nm2 = m1; ni2 = i1; }
                else                          { nm2 = om2; ni2 = oi2; }
                m1 = om1; i1 = oi1; m2 = nm2; i2 = ni2;
            } else {
                if (better(om1, oi1, m2, i2)) { m2 = om1; i2 = oi1; }
            }
        }
        if ((lane & 3) == 0) {
            // top-2 renorm of full softmax == logistic of (m1 - m2); +1e-9 negligible
            float e2 = __expf(m2 - m1);
            float rcp = 1.0f / (1.0f + e2);
            out[(size_t)row * 2 + 0] = (float)i1;
            out[(size_t)row * 2 + 1] = (float)i2;
            out[2 * TOKENS + (size_t)row * 2 + 0] = rcp;
            out[2 * TOKENS + (size_t)row * 2 + 1] = e2 * rcp;
        }
    }
}

extern "C" void kernel_launch(void* const* d_in, const int* in_sizes, int n_in,
                              void* d_out, int out_size)
{
    const float* x  = (const float*)d_in[0];
    const float* Wg = (const float*)d_in[1];
    float* out = (float*)d_out;

    cudaFuncSetAttribute(router_kernel, cudaFuncAttributeMaxDynamicSharedMemorySize, SMEM_BYTES);

    convert_w_kernel<<<256, 256>>>(Wg);
    router_kernel<<<TOKENS / 16, 128, SMEM_BYTES>>>(x, out);
}

// round 11
// speedup vs baseline: 2.5136x; 1.9477x over previous
#include <cuda_runtime.h>
#include <cuda_bf16.h>
#include <math.h>
#include <stdint.h>

// TopKRouter: logits = x @ W^T (16384x4096 @ 4096x64), softmax, top-2, renorm.
// Split-bf16 (hi/lo) 3-product mma.sync.m16n8k16 GEMM, K-split x4 across warps.
// Round 11: R6 shape + __launch_bounds__(128,3) (<=170 regs, 12 warps/SM) and an
//           explicit 1-step register double-buffer for A and B so a full step's
//           12 loads are always in flight behind the 24 MMAs.
// out fp32: [indices 16384*2][weights 16384*2][logits 16384*64]

#define TOKENS 16384
#define DIM    4096
#define NEXP   64
#define NKS    (DIM / 16)   // 256 k-steps total
#define KSW    (NKS / 4)    // 64 k-steps per warp

// Fragment-ordered pre-converted W, hi and lo interleaved:
// q = ((ks*8 + nt)*32 + lane): uint4 { hi(kb,kb+1), hi(kb+8,kb+9),
//                                      lo(kb,kb+1), lo(kb+8,kb+9) }
// with n = nt*8 + lane/4, kb = ks*16 + (lane%4)*2.
__device__ uint4 g_B[NKS * 8 * 32];

__device__ __forceinline__ void split2(float a, float b, unsigned& h, unsigned& l) {
    asm("cvt.rn.bf16x2.f32 %0, %1, %2;" : "=r"(h) : "f"(b), "f"(a));
    float ha = __uint_as_float(h << 16);
    float hb = __uint_as_float(h & 0xFFFF0000u);
    float ra = a - ha;
    float rb = b - hb;
    asm("cvt.rn.bf16x2.f32 %0, %1, %2;" : "=r"(l) : "f"(rb), "f"(ra));
}

__device__ __forceinline__ void mma16816(float* c, unsigned a0, unsigned a1,
                                         unsigned a2, unsigned a3,
                                         unsigned b0, unsigned b1) {
    asm volatile(
        "mma.sync.aligned.m16n8k16.row.col.f32.bf16.bf16.f32 "
        "{%0,%1,%2,%3}, {%4,%5,%6,%7}, {%8,%9}, {%0,%1,%2,%3};"
        : "+f"(c[0]), "+f"(c[1]), "+f"(c[2]), "+f"(c[3])
        : "r"(a0), "r"(a1), "r"(a2), "r"(a3), "r"(b0), "r"(b1));
}

// ---------------- W pre-convert (fragment order, interleaved) ----------------
__global__ void convert_w_kernel(const float* __restrict__ Wg) {
    int q = blockIdx.x * blockDim.x + threadIdx.x;   // 0..65535
    int ks   = q >> 8;
    int nt   = (q >> 5) & 7;
    int lane = q & 31;
    int n  = nt * 8 + (lane >> 2);
    int kb = ks * 16 + (lane & 3) * 2;
    const float* wr = Wg + (size_t)n * DIM + kb;
    unsigned hx, lx, hy, ly;
    split2(wr[0], wr[1], hx, lx);
    split2(wr[8], wr[9], hy, ly);
    g_B[q] = make_uint4(hx, hy, lx, ly);
}

__device__ __forceinline__ bool better(float v, int i, float v2, int i2) {
    return (v > v2) || (v == v2 && i < i2);
}

// ---------------- main kernel ----------------
// CTA: 4 warps, same 16 tokens, K quarters. Partial-acc reduce through smem.
__global__ __launch_bounds__(128, 3) void router_kernel(
    const float* __restrict__ x,
    float* __restrict__ out)
{
    __shared__ float red[3 * 32 * 33];   // 3 partials x 32 lanes x 32 floats, pad 33

    const int tid  = threadIdx.x;
    const int wid  = tid >> 5;           // K quarter 0..3
    const int lane = tid & 31;
    const int r0   = blockIdx.x * 16 + (lane >> 2);   // rows r0, r0+8
    const int kbase = wid * KSW;

    const float2* pA0 = (const float2*)(x + (size_t)r0 * DIM) + (lane & 3);
    const float2* pA1 = pA0 + 4 * DIM;   // row r0+8

    float acc[8][4];
    #pragma unroll
    for (int nt = 0; nt < 8; nt++)
        #pragma unroll
        for (int j = 0; j < 4; j++) acc[nt][j] = 0.0f;

    const uint4* __restrict__ B = g_B + lane;

    // ---- prime the register double-buffer with step kbase ----
    float2 nA00 = __ldg(pA0 + kbase * 8);
    float2 nA01 = __ldg(pA0 + kbase * 8 + 4);
    float2 nA10 = __ldg(pA1 + kbase * 8);
    float2 nA11 = __ldg(pA1 + kbase * 8 + 4);
    uint4 nB[8];
    #pragma unroll
    for (int nt = 0; nt < 8; nt++)
        nB[nt] = __ldg(B + kbase * 256 + nt * 32);

    for (int s = 0; s < KSW; s++) {
        // consume-copies (register renames)
        float2 v00 = nA00, v01 = nA01, v10 = nA10, v11 = nA11;
        uint4 cB[8];
        #pragma unroll
        for (int nt = 0; nt < 8; nt++) cB[nt] = nB[nt];

        // issue next step's loads (wrap on last iter: harmless redundant reload)
        const int ks2 = kbase + ((s + 1) & (KSW - 1));
        nA00 = __ldg(pA0 + ks2 * 8);
        nA01 = __ldg(pA0 + ks2 * 8 + 4);
        nA10 = __ldg(pA1 + ks2 * 8);
        nA11 = __ldg(pA1 + ks2 * 8 + 4);
        #pragma unroll
        for (int nt = 0; nt < 8; nt++)
            nB[nt] = __ldg(B + ks2 * 256 + nt * 32);

        unsigned ah0, ah1, ah2, ah3, al0, al1, al2, al3;
        split2(v00.x, v00.y, ah0, al0);
        split2(v10.x, v10.y, ah1, al1);
        split2(v01.x, v01.y, ah2, al2);
        split2(v11.x, v11.y, ah3, al3);

        #pragma unroll
        for (int nt = 0; nt < 8; nt++) {
            mma16816(acc[nt], ah0, ah1, ah2, ah3, cB[nt].x, cB[nt].y);   // hi*hi
            mma16816(acc[nt], ah0, ah1, ah2, ah3, cB[nt].z, cB[nt].w);   // hi*lo
            mma16816(acc[nt], al0, al1, al2, al3, cB[nt].x, cB[nt].y);   // lo*hi
        }
    }

    // ---- cross-warp K reduction via smem ----
    if (wid != 0) {
        float* dst = red + ((wid - 1) * 32 + lane) * 33;
        #pragma unroll
        for (int nt = 0; nt < 8; nt++)
            #pragma unroll
            for (int j = 0; j < 4; j++)
                dst[nt * 4 + j] = acc[nt][j];
    }
    __syncthreads();
    if (wid != 0) return;

    #pragma unroll
    for (int p = 0; p < 3; p++) {
        const float* src = red + (p * 32 + lane) * 33;
        #pragma unroll
        for (int nt = 0; nt < 8; nt++)
            #pragma unroll
            for (int j = 0; j < 4; j++)
                acc[nt][j] += src[nt * 4 + j];
    }

    // ---- write logits ----
    float* lg = out + 4 * TOKENS;
    const int cbase = (lane & 3) * 2;
    #pragma unroll
    for (int nt = 0; nt < 8; nt++) {
        int c = nt * 8 + cbase;
        *(float2*)(lg + (size_t)r0 * NEXP + c)       = make_float2(acc[nt][0], acc[nt][1]);
        *(float2*)(lg + (size_t)(r0 + 8) * NEXP + c) = make_float2(acc[nt][2], acc[nt][3]);
    }

    // ---- per-row top-2 (register scan + quad shuffle merge) ----
    #pragma unroll
    for (int half = 0; half < 2; half++) {
        const int row = r0 + half * 8;
        float m1 = -INFINITY, m2 = -INFINITY;
        int i1 = 0, i2 = 0;
        #pragma unroll
        for (int nt = 0; nt < 8; nt++) {
            #pragma unroll
            for (int j = 0; j < 2; j++) {
                float v = acc[nt][half * 2 + j];
                int e = nt * 8 + cbase + j;
                if (v > m1)      { m2 = m1; i2 = i1; m1 = v; i1 = e; }
                else if (v > m2) { m2 = v; i2 = e; }
            }
        }
        #pragma unroll
        for (int d = 1; d < 4; d <<= 1) {
            float om1 = __shfl_xor_sync(0xFFFFFFFF, m1, d);
            int   oi1 = __shfl_xor_sync(0xFFFFFFFF, i1, d);
            float om2 = __shfl_xor_sync(0xFFFFFFFF, m2, d);
            int   oi2 = __shfl_xor_sync(0xFFFFFFFF, i2, d);
            if (better(om1, oi1, m1, i1)) {
                float nm2; int ni2;
                if (better(m1, i1, om2, oi2)) { nm2 = m1; ni2 = i1; }
                else                          { nm2 = om2; ni2 = oi2; }
                m1 = om1; i1 = oi1; m2 = nm2; i2 = ni2;
            } else {
                if (better(om1, oi1, m2, i2)) { m2 = om1; i2 = oi1; }
            }
        }
        if ((lane & 3) == 0) {
            // top-2 renorm of full softmax == logistic of (m1 - m2); +1e-9 negligible
            float e2 = __expf(m2 - m1);
            float rcp = 1.0f / (1.0f + e2);
            out[(size_t)row * 2 + 0] = (float)i1;
            out[(size_t)row * 2 + 1] = (float)i2;
            out[2 * TOKENS + (size_t)row * 2 + 0] = rcp;
            out[2 * TOKENS + (size_t)row * 2 + 1] = e2 * rcp;
        }
    }
}

extern "C" void kernel_launch(void* const* d_in, const int* in_sizes, int n_in,
                              void* d_out, int out_size)
{
    const float* x  = (const float*)d_in[0];
    const float* Wg = (const float*)d_in[1];
    float* out = (float*)d_out;

    convert_w_kernel<<<256, 256>>>(Wg);
    router_kernel<<<TOKENS / 16, 128>>>(x, out);
}